// round 6
// baseline (speedup 1.0000x reference)
#include <cuda_runtime.h>
#include <cuda_bf16.h>

// Problem constants
#define BB 2
#define TT 4096
#define EE 768
#define HH 12
#define SS 64
#define WW 256
#define CC 16
#define NN (BB * TT)   // 8192

// ---------------------------------------------------------------------------
// Planar split-bf16 scratch: hi plane = bf16(x), lo plane = bf16(x - hi)
// ---------------------------------------------------------------------------
__device__ __nv_bfloat16 g_xh[(size_t)NN * EE], g_xl[(size_t)NN * EE];
__device__ __nv_bfloat16 g_wh[(size_t)3 * EE * EE], g_wl[(size_t)3 * EE * EE];
__device__ __nv_bfloat16 g_qh[(size_t)BB * HH * TT * SS], g_ql[(size_t)BB * HH * TT * SS];
__device__ __nv_bfloat16 g_kh[(size_t)BB * HH * TT * SS], g_kl[(size_t)BB * HH * TT * SS];
__device__ __nv_bfloat16 g_vh[(size_t)BB * HH * TT * SS], g_vl[(size_t)BB * HH * TT * SS];

// ---------------------------------------------------------------------------
// Helpers
// ---------------------------------------------------------------------------
__device__ __forceinline__ unsigned pack2bf(float lo_elem, float hi_elem) {
    unsigned r;
    asm("cvt.rn.bf16x2.f32 %0, %1, %2;" : "=r"(r) : "f"(hi_elem), "f"(lo_elem));
    return r;
}
__device__ __forceinline__ unsigned smaddr(const void* p) {
    return (unsigned)__cvta_generic_to_shared(p);
}
__device__ __forceinline__ void cp16(unsigned dst, const void* src) {
    asm volatile("cp.async.cg.shared.global [%0], [%1], 16;" :: "r"(dst), "l"(src));
}
#define CP_COMMIT asm volatile("cp.async.commit_group;")
#define CP_WAIT0  asm volatile("cp.async.wait_group 0;")
#define CP_WAIT1  asm volatile("cp.async.wait_group 1;")
__device__ __forceinline__ void ldm_x4(unsigned a, unsigned& r0, unsigned& r1,
                                       unsigned& r2, unsigned& r3) {
    asm volatile("ldmatrix.sync.aligned.m8n8.x4.shared.b16 {%0,%1,%2,%3},[%4];"
                 : "=r"(r0), "=r"(r1), "=r"(r2), "=r"(r3) : "r"(a));
}
__device__ __forceinline__ void ldm_x4t(unsigned a, unsigned& r0, unsigned& r1,
                                        unsigned& r2, unsigned& r3) {
    asm volatile("ldmatrix.sync.aligned.m8n8.x4.trans.shared.b16 {%0,%1,%2,%3},[%4];"
                 : "=r"(r0), "=r"(r1), "=r"(r2), "=r"(r3) : "r"(a));
}
__device__ __forceinline__ void mma_bf16(float* d, const unsigned* a,
                                         unsigned b0, unsigned b1) {
    asm volatile(
        "mma.sync.aligned.m16n8k16.row.col.f32.bf16.bf16.f32 "
        "{%0,%1,%2,%3},{%4,%5,%6,%7},{%8,%9},{%0,%1,%2,%3};"
        : "+f"(d[0]), "+f"(d[1]), "+f"(d[2]), "+f"(d[3])
        : "r"(a[0]), "r"(a[1]), "r"(a[2]), "r"(a[3]), "r"(b0), "r"(b1));
}

// ---------------------------------------------------------------------------
// Pass 0: fp32 -> planar split bf16 (one launch for x, wq, wk, wv)
// ---------------------------------------------------------------------------
#define NX4 (NN * EE / 4)
#define NW4 (EE * EE / 4)
#define NTOT4 (NX4 + 3 * NW4)

__global__ __launch_bounds__(256) void convert_kernel(
    const float* __restrict__ x,  const float* __restrict__ wq,
    const float* __restrict__ wk, const float* __restrict__ wv)
{
    int i = blockIdx.x * 256 + threadIdx.x;
    if (i >= NTOT4) return;
    const float4* src;
    __nv_bfloat16 *dh, *dl;
    int j;
    if (i < NX4)                { src = (const float4*)x;  dh = g_xh;              dl = g_xl;              j = i; }
    else if (i < NX4 + NW4)     { src = (const float4*)wq; dh = g_wh;              dl = g_wl;              j = i - NX4; }
    else if (i < NX4 + 2 * NW4) { src = (const float4*)wk; dh = g_wh + EE * EE;     dl = g_wl + EE * EE;     j = i - NX4 - NW4; }
    else                        { src = (const float4*)wv; dh = g_wh + 2 * EE * EE; dl = g_wl + 2 * EE * EE; j = i - NX4 - 2 * NW4; }
    float4 v = src[j];
    float hx = __bfloat162float(__float2bfloat16(v.x));
    float hy = __bfloat162float(__float2bfloat16(v.y));
    float hz = __bfloat162float(__float2bfloat16(v.z));
    float hw = __bfloat162float(__float2bfloat16(v.w));
    uint2 ho, lo;
    ho.x = pack2bf(v.x, v.y);        ho.y = pack2bf(v.z, v.w);
    lo.x = pack2bf(v.x - hx, v.y - hy); lo.y = pack2bf(v.z - hz, v.w - hw);
    ((uint2*)dh)[j] = ho;
    ((uint2*)dl)[j] = lo;
}

// ---------------------------------------------------------------------------
// Pass 1: Q/K/V GEMM, cp.async double-buffered, k-step 32.
// 128x128 tile, 8 warps (2x4), warp 64x32, 3-term split mma.
// Smem plane: 128 rows x 40 elems (80B stride, conflict-free rotation).
// ---------------------------------------------------------------------------
#define QP_ST    80                      // bytes per row
#define QP_PLANE (128 * QP_ST)           // 10240 B
#define QP_STAGE (4 * QP_PLANE)          // AH AL BH BL
#define QKV_SMEM (2 * QP_STAGE)          // 81920 B

__global__ __launch_bounds__(256) void qkv_mma_kernel()
{
    extern __shared__ char smraw[];
    const unsigned su = smaddr(smraw);

    const int which = blockIdx.z;
    const __nv_bfloat16* wph = g_wh + (size_t)which * EE * EE;
    const __nv_bfloat16* wpl = g_wl + (size_t)which * EE * EE;
    __nv_bfloat16* dsth = (which == 0) ? g_qh : (which == 1) ? g_kh : g_vh;
    __nv_bfloat16* dstl = (which == 0) ? g_ql : (which == 1) ? g_kl : g_vl;
    const float scale = (which == 0) ? 0.125f : 1.0f;

    const int rowBase = blockIdx.x * 128;
    const int colBase = blockIdx.y * 128;
    const int t    = threadIdx.x;
    const int lane = t & 31;
    const int w    = t >> 5;
    const int wm   = (w >> 2) * 64;
    const int wn   = (w & 3) * 32;

    float acc[4][4][4];
    #pragma unroll
    for (int mt = 0; mt < 4; mt++)
        #pragma unroll
        for (int nt = 0; nt < 4; nt++)
            #pragma unroll
            for (int e = 0; e < 4; e++) acc[mt][nt][e] = 0.0f;

    // --- stage issue: 8 cp.async per thread (4 planes x 2 granules) ---
    #define QKV_ISSUE(BUF, K0)                                                  \
    {                                                                           \
        const unsigned base = su + (BUF) * QP_STAGE;                            \
        _Pragma("unroll")                                                       \
        for (int j = 0; j < 2; j++) {                                           \
            const int gi  = t + j * 256;                                        \
            const int row = gi >> 2;                                            \
            const int gc  = gi & 3;                                             \
            const unsigned d = row * QP_ST + gc * 16;                           \
            const size_t sa = (size_t)(rowBase + row) * EE + (K0) + gc * 8;     \
            const size_t sb = (size_t)(colBase + row) * EE + (K0) + gc * 8;     \
            cp16(base + d,                 g_xh + sa);                          \
            cp16(base + QP_PLANE + d,      g_xl + sa);                          \
            cp16(base + 2 * QP_PLANE + d,  wph + sb);                           \
            cp16(base + 3 * QP_PLANE + d,  wpl + sb);                           \
        }                                                                       \
    }

    QKV_ISSUE(0, 0); CP_COMMIT;

    for (int kt = 0; kt < 24; kt++) {
        const int buf = kt & 1;
        if (kt + 1 < 24) { QKV_ISSUE(buf ^ 1, (kt + 1) * 32); CP_COMMIT; CP_WAIT1; }
        else             { CP_WAIT0; }
        __syncthreads();

        const unsigned base = su + buf * QP_STAGE;
        #pragma unroll
        for (int ks = 0; ks < 2; ks++) {
            unsigned ah[4][4], al[4][4], bh[2][4], bl[2][4];
            #pragma unroll
            for (int mt = 0; mt < 4; mt++) {
                const unsigned off = (wm + mt * 16 + (lane & 15)) * QP_ST
                                   + (ks * 16 + ((lane >> 4) << 3)) * 2;
                ldm_x4(base + off,            ah[mt][0], ah[mt][1], ah[mt][2], ah[mt][3]);
                ldm_x4(base + QP_PLANE + off, al[mt][0], al[mt][1], al[mt][2], al[mt][3]);
            }
            #pragma unroll
            for (int g = 0; g < 2; g++) {
                const unsigned off = (wn + g * 16 + ((lane >> 4) << 3) + (lane & 7)) * QP_ST
                                   + (ks * 16 + (((lane >> 3) & 1) << 3)) * 2;
                ldm_x4(base + 2 * QP_PLANE + off, bh[g][0], bh[g][1], bh[g][2], bh[g][3]);
                ldm_x4(base + 3 * QP_PLANE + off, bl[g][0], bl[g][1], bl[g][2], bl[g][3]);
            }
            #pragma unroll
            for (int mt = 0; mt < 4; mt++)
                #pragma unroll
                for (int nt = 0; nt < 4; nt++) {
                    const int g  = nt >> 1;
                    const int hb = (nt & 1) * 2;
                    mma_bf16(acc[mt][nt], ah[mt], bh[g][hb], bh[g][hb + 1]);
                    mma_bf16(acc[mt][nt], al[mt], bh[g][hb], bh[g][hb + 1]);
                    mma_bf16(acc[mt][nt], ah[mt], bl[g][hb], bl[g][hb + 1]);
                }
        }
        __syncthreads();
    }

    // epilogue: planar split store [b][h][t][d]
    #pragma unroll
    for (int mt = 0; mt < 4; mt++) {
        const int rg0 = rowBase + wm + mt * 16 + (lane >> 2);
        #pragma unroll
        for (int nt = 0; nt < 4; nt++) {
            const int jc = colBase + wn + nt * 8 + (lane & 3) * 2;
            const int h  = jc >> 6;
            const int d  = jc & 63;
            #pragma unroll
            for (int rh = 0; rh < 2; rh++) {
                const int rg = rg0 + rh * 8;
                const int bb = rg >> 12;
                const int tt = rg & (TT - 1);
                const size_t idx = (((size_t)(bb * HH + h) * TT) + tt) * SS + d;
                const float v0 = acc[mt][nt][rh * 2 + 0] * scale;
                const float v1 = acc[mt][nt][rh * 2 + 1] * scale;
                const float h0 = __bfloat162float(__float2bfloat16(v0));
                const float h1 = __bfloat162float(__float2bfloat16(v1));
                *(unsigned*)&dsth[idx] = pack2bf(v0, v1);
                *(unsigned*)&dstl[idx] = pack2bf(v0 - h0, v1 - h1);
            }
        }
    }
}

// ---------------------------------------------------------------------------
// Pass 2: fused flash attention, cp.async double-buffered over valid tiles.
// Block = 128 q x (b,h); 8 warps x 16 q-rows. Boundary chunks handled
// analytically (n0 unmasked zero-scores per row). Smem plane: 128 x 144B.
// ---------------------------------------------------------------------------
#define AP_ST    144
#define AP_PLANE (128 * AP_ST)           // 18432 B
#define AP_STAGE (4 * AP_PLANE)          // KH KL VH VL
#define ATT_SMEM (2 * AP_STAGE)          // 147456 B

__global__ __launch_bounds__(256) void attn_mma_kernel(float* __restrict__ out)
{
    extern __shared__ char smraw[];
    const unsigned su = smaddr(smraw);

    const int c    = blockIdx.x >> 1;
    const int half = blockIdx.x & 1;
    const int bh   = blockIdx.y;
    const int b = bh / HH;
    const int h = bh % HH;

    const int t    = threadIdx.x;
    const int lane = t & 31;
    const int w    = t >> 5;

    // ---- stage Q planes into stage-0 KH/KL, build Q frags ----
    {
        const size_t qoff = ((size_t)bh * TT + c * WW + half * 128) * SS;
        #pragma unroll
        for (int j = 0; j < 4; j++) {
            const int gi  = t + j * 256;          // 0..1023
            const int row = gi >> 3;
            const int gc  = gi & 7;
            const unsigned d = row * AP_ST + gc * 16;
            const size_t s = qoff + (size_t)row * SS + gc * 8;
            cp16(su + d,            g_qh + s);
            cp16(su + AP_PLANE + d, g_ql + s);
        }
        CP_COMMIT; CP_WAIT0;
    }
    __syncthreads();

    unsigned qh[4][4], ql[4][4];
    #pragma unroll
    for (int kt = 0; kt < 4; kt++) {
        const unsigned off = (w * 16 + (lane & 15)) * AP_ST
                           + (kt * 16 + ((lane >> 4) << 3)) * 2;
        ldm_x4(su + off,            qh[kt][0], qh[kt][1], qh[kt][2], qh[kt][3]);
        ldm_x4(su + AP_PLANE + off, ql[kt][0], ql[kt][1], ql[kt][2], ql[kt][3]);
    }
    __syncthreads();

    float m0 = -1e30f, m1 = -1e30f, l0 = 0.0f, l1 = 0.0f;
    float o_fr[8][4];
    #pragma unroll
    for (int nd = 0; nd < 8; nd++)
        #pragma unroll
        for (int e = 0; e < 4; e++) o_fr[nd][e] = 0.0f;

    const int r0 = half * 128 + w * 16 + (lane >> 2);  // row in chunk, frag row 0
    const int r1 = r0 + 8;

    // ---- analytic boundary-chunk contribution (scores all 0 or masked) ----
    if (c == 0) {
        if (r0 > 0) { m0 = 0.0f; l0 = (float)r0; }
        if (r1 > 0) { m1 = 0.0f; l1 = (float)r1; }
    } else if (c == CC - 1) {
        const int a0 = 255 - r0, a1 = 255 - r1;
        if (a0 > 0) { m0 = 0.0f; l0 = (float)a0; }
        if (a1 > 0) { m1 = 0.0f; l1 = (float)a1; }
    }

    const int tstart = (c == 0) ? 2 : 0;
    const int tend   = (c == CC - 1) ? 4 : 6;

    #define ATT_ISSUE(BUF, NT)                                                  \
    {                                                                           \
        const int kc_ = c - 1 + ((NT) >> 1);                                    \
        const size_t koff = ((size_t)bh * TT + kc_ * WW + ((NT) & 1) * 128) * SS; \
        const unsigned base = su + (BUF) * AP_STAGE;                            \
        _Pragma("unroll")                                                       \
        for (int j = 0; j < 4; j++) {                                           \
            const int gi  = t + j * 256;                                        \
            const int row = gi >> 3;                                            \
            const int gc  = gi & 7;                                             \
            const unsigned d = row * AP_ST + gc * 16;                           \
            const size_t s = koff + (size_t)row * SS + gc * 8;                  \
            cp16(base + d,                 g_kh + s);                           \
            cp16(base + AP_PLANE + d,      g_kl + s);                           \
            cp16(base + 2 * AP_PLANE + d,  g_vh + s);                           \
            cp16(base + 3 * AP_PLANE + d,  g_vl + s);                           \
        }                                                                       \
    }

    ATT_ISSUE(0, tstart); CP_COMMIT;

    for (int nt = tstart; nt < tend; nt++) {
        const int buf = (nt - tstart) & 1;
        if (nt + 1 < tend) { ATT_ISSUE(buf ^ 1, nt + 1); CP_COMMIT; CP_WAIT1; }
        else               { CP_WAIT0; }
        __syncthreads();

        const unsigned base = su + buf * AP_STAGE;
        float s_fr[16][4];
        #pragma unroll
        for (int n = 0; n < 16; n++)
            #pragma unroll
            for (int e = 0; e < 4; e++) s_fr[n][e] = 0.0f;

        // ---- QK ----
        #pragma unroll
        for (int kt = 0; kt < 4; kt++) {
            #pragma unroll
            for (int g = 0; g < 8; g++) {
                unsigned kbf[4], klf[4];
                const unsigned off = (g * 16 + ((lane >> 4) << 3) + (lane & 7)) * AP_ST
                                   + (kt * 16 + (((lane >> 3) & 1) << 3)) * 2;
                ldm_x4(base + off,            kbf[0], kbf[1], kbf[2], kbf[3]);
                ldm_x4(base + AP_PLANE + off, klf[0], klf[1], klf[2], klf[3]);
                #pragma unroll
                for (int h2 = 0; h2 < 2; h2++) {
                    const int n = g * 2 + h2;
                    mma_bf16(s_fr[n], qh[kt], kbf[h2 * 2], kbf[h2 * 2 + 1]);
                    mma_bf16(s_fr[n], ql[kt], kbf[h2 * 2], kbf[h2 * 2 + 1]);
                    mma_bf16(s_fr[n], qh[kt], klf[h2 * 2], klf[h2 * 2 + 1]);
                }
            }
        }

        // ---- online softmax ----
        float rm0 = -1e30f, rm1 = -1e30f;
        #pragma unroll
        for (int n = 0; n < 16; n++) {
            rm0 = fmaxf(rm0, fmaxf(s_fr[n][0], s_fr[n][1]));
            rm1 = fmaxf(rm1, fmaxf(s_fr[n][2], s_fr[n][3]));
        }
        #pragma unroll
        for (int off = 1; off <= 2; off <<= 1) {
            rm0 = fmaxf(rm0, __shfl_xor_sync(0xFFFFFFFFu, rm0, off));
            rm1 = fmaxf(rm1, __shfl_xor_sync(0xFFFFFFFFu, rm1, off));
        }
        const float mn0 = fmaxf(m0, rm0);
        const float mn1 = fmaxf(m1, rm1);
        const float al0 = __expf(m0 - mn0);
        const float al1 = __expf(m1 - mn1);
        float rs0 = 0.0f, rs1 = 0.0f;
        #pragma unroll
        for (int n = 0; n < 16; n++) {
            s_fr[n][0] = __expf(s_fr[n][0] - mn0);
            s_fr[n][1] = __expf(s_fr[n][1] - mn0);
            s_fr[n][2] = __expf(s_fr[n][2] - mn1);
            s_fr[n][3] = __expf(s_fr[n][3] - mn1);
            rs0 += s_fr[n][0] + s_fr[n][1];
            rs1 += s_fr[n][2] + s_fr[n][3];
        }
        #pragma unroll
        for (int off = 1; off <= 2; off <<= 1) {
            rs0 += __shfl_xor_sync(0xFFFFFFFFu, rs0, off);
            rs1 += __shfl_xor_sync(0xFFFFFFFFu, rs1, off);
        }
        l0 = l0 * al0 + rs0;  m0 = mn0;
        l1 = l1 * al1 + rs1;  m1 = mn1;
        #pragma unroll
        for (int nd = 0; nd < 8; nd++) {
            o_fr[nd][0] *= al0; o_fr[nd][1] *= al0;
            o_fr[nd][2] *= al1; o_fr[nd][3] *= al1;
        }

        // ---- PV ----
        #pragma unroll
        for (int ktj = 0; ktj < 8; ktj++) {
            const float* pe = s_fr[2 * ktj];
            const float* po = s_fr[2 * ktj + 1];
            const float heA = __bfloat162float(__float2bfloat16(pe[0]));
            const float heB = __bfloat162float(__float2bfloat16(pe[1]));
            const float heC = __bfloat162float(__float2bfloat16(pe[2]));
            const float heD = __bfloat162float(__float2bfloat16(pe[3]));
            const float hoA = __bfloat162float(__float2bfloat16(po[0]));
            const float hoB = __bfloat162float(__float2bfloat16(po[1]));
            const float hoC = __bfloat162float(__float2bfloat16(po[2]));
            const float hoD = __bfloat162float(__float2bfloat16(po[3]));
            unsigned pah[4], pal[4];
            pah[0] = pack2bf(pe[0], pe[1]);
            pah[1] = pack2bf(pe[2], pe[3]);
            pah[2] = pack2bf(po[0], po[1]);
            pah[3] = pack2bf(po[2], po[3]);
            pal[0] = pack2bf(pe[0] - heA, pe[1] - heB);
            pal[1] = pack2bf(pe[2] - heC, pe[3] - heD);
            pal[2] = pack2bf(po[0] - hoA, po[1] - hoB);
            pal[3] = pack2bf(po[2] - hoC, po[3] - hoD);

            #pragma unroll
            for (int g = 0; g < 4; g++) {
                unsigned vbf[4], vlf[4];
                const unsigned off = (ktj * 16 + (lane & 15)) * AP_ST
                                   + (g * 16 + ((lane >> 4) << 3)) * 2;
                ldm_x4t(base + 2 * AP_PLANE + off, vbf[0], vbf[1], vbf[2], vbf[3]);
                ldm_x4t(base + 3 * AP_PLANE + off, vlf[0], vlf[1], vlf[2], vlf[3]);
                #pragma unroll
                for (int h2 = 0; h2 < 2; h2++) {
                    const int nd = g * 2 + h2;
                    mma_bf16(o_fr[nd], pah, vbf[h2 * 2], vbf[h2 * 2 + 1]);
                    mma_bf16(o_fr[nd], pal, vbf[h2 * 2], vbf[h2 * 2 + 1]);
                    mma_bf16(o_fr[nd], pah, vlf[h2 * 2], vlf[h2 * 2 + 1]);
                }
            }
        }
        __syncthreads();
    }

    // ---- epilogue ----
    const float inv0 = 1.0f / l0;
    const float inv1 = 1.0f / l1;
    const int tr0 = c * WW + half * 128 + w * 16 + (lane >> 2);
    #pragma unroll
    for (int nd = 0; nd < 8; nd++) {
        const int d0 = nd * 8 + (lane & 3) * 2;
        *(float2*)&out[((size_t)b * TT + tr0) * EE + h * SS + d0] =
            make_float2(o_fr[nd][0] * inv0, o_fr[nd][1] * inv0);
        *(float2*)&out[((size_t)b * TT + tr0 + 8) * EE + h * SS + d0] =
            make_float2(o_fr[nd][2] * inv1, o_fr[nd][3] * inv1);
    }
}

// ---------------------------------------------------------------------------
extern "C" void kernel_launch(void* const* d_in, const int* in_sizes, int n_in,
                              void* d_out, int out_size)
{
    const float* x  = (const float*)d_in[0];
    const float* wq = (const float*)d_in[1];
    const float* wk = (const float*)d_in[2];
    const float* wv = (const float*)d_in[3];
    float* out = (float*)d_out;

    cudaFuncSetAttribute(qkv_mma_kernel,
                         cudaFuncAttributeMaxDynamicSharedMemorySize, QKV_SMEM);
    cudaFuncSetAttribute(attn_mma_kernel,
                         cudaFuncAttributeMaxDynamicSharedMemorySize, ATT_SMEM);

    convert_kernel<<<(NTOT4 + 255) / 256, 256>>>(x, wq, wk, wv);
    qkv_mma_kernel<<<dim3(NN / 128, EE / 128, 3), 256, QKV_SMEM>>>();
    attn_mma_kernel<<<dim3(2 * CC, BB * HH), 256, ATT_SMEM>>>(out);
}